// round 5
// baseline (speedup 1.0000x reference)
#include <cuda_runtime.h>
#include <math.h>

#define T_  128
#define B_  128
#define I_  128
#define H_  512
#define W_  16
#define G4  2048
#define BH  65536
#define TB  16384
#define NCTA 148
#define INV_SQRT_DK 0.04419417382415922f

// ---------------- device scratch (static) -----------------------------------
__device__ float g_XWi[(size_t)TB * G4];   // x@Wi + (bi+ba+bv@Wa)
__device__ float g_XQV[(size_t)TB * H_];   // x@(Wqx@WvT)
__device__ float g_WhWa[1024 * G4];        // [Wh ; Wv@Wa]
__device__ float g_Wqv[H_ * H_];           // Wqh@WvT
__device__ float g_Wqxv[I_ * H_];          // Wqx@WvT
__device__ float g_WvT[H_ * H_];
__device__ float g_bia[G4];
__device__ float g_bqv[H_];                // bq@WvT
__device__ float g_wqb[H_];                // Wqh@bv
__device__ float g_u[I_];                  // Wqx@bv
__device__ float g_sbq;                    // bq.bv
__device__ float g_h[BH];
__device__ float g_c[BH];
__device__ float g_HA[B_ * 1024];          // [h | cbar]
__device__ float g_Cbuf[W_ * BH];          // c history ring
__device__ float g_Qp[8 * BH];             // Qv split-K partials
__device__ float g_Pre[2 * B_ * G4];       // preact split-K partials
__device__ volatile unsigned g_flags[NCTA * 32];

// ---------------- fp32 tiled GEMM body: 64x64 tile, 256 thr, 4x4/thr --------
__device__ __forceinline__ void gemm_body(
    const float* __restrict__ A, int lda,
    const float* __restrict__ B, int ldb,
    float* __restrict__ C, int ldc,
    const float* __restrict__ bias,
    int m0, int n0, int nk)
{
    __shared__ float As[2][16][68];
    __shared__ float Bs[2][16][64];
    const int tid = threadIdx.x;
    const int ar = tid >> 2;
    const int ac = (tid & 3) << 2;
    const int br = tid >> 4;
    const int bc = (tid & 15) << 2;
    const float* Aptr = A + (size_t)(m0 + ar) * lda + ac;
    const float* Bptr = B + (size_t)br * ldb + n0 + bc;
    float4 ra = *(const float4*)Aptr;
    float4 rb = *(const float4*)Bptr;
    const int tm = (tid >> 4) << 2;
    const int tn = (tid & 15) << 2;
    float acc[4][4];
#pragma unroll
    for (int i = 0; i < 4; i++)
#pragma unroll
        for (int j = 0; j < 4; j++) acc[i][j] = 0.f;

    int buf = 0;
    for (int kt = 0; kt < nk; kt++) {
        As[buf][ac + 0][ar] = ra.x;
        As[buf][ac + 1][ar] = ra.y;
        As[buf][ac + 2][ar] = ra.z;
        As[buf][ac + 3][ar] = ra.w;
        *(float4*)&Bs[buf][br][bc] = rb;
        __syncthreads();
        if (kt + 1 < nk) {
            ra = *(const float4*)(Aptr + (kt + 1) * 16);
            rb = *(const float4*)(Bptr + (size_t)(kt + 1) * 16 * ldb);
        }
#pragma unroll
        for (int kk = 0; kk < 16; kk++) {
            float4 a = *(const float4*)(&As[buf][kk][tm]);
            float4 b = *(const float4*)(&Bs[buf][kk][tn]);
            acc[0][0] += a.x * b.x; acc[0][1] += a.x * b.y; acc[0][2] += a.x * b.z; acc[0][3] += a.x * b.w;
            acc[1][0] += a.y * b.x; acc[1][1] += a.y * b.y; acc[1][2] += a.y * b.z; acc[1][3] += a.y * b.w;
            acc[2][0] += a.z * b.x; acc[2][1] += a.z * b.y; acc[2][2] += a.z * b.z; acc[2][3] += a.z * b.w;
            acc[3][0] += a.w * b.x; acc[3][1] += a.w * b.y; acc[3][2] += a.w * b.z; acc[3][3] += a.w * b.w;
        }
        buf ^= 1;
    }
    float4 bv4 = make_float4(0.f, 0.f, 0.f, 0.f);
    if (bias) bv4 = *(const float4*)(bias + n0 + tn);
#pragma unroll
    for (int i = 0; i < 4; i++) {
        float4 v;
        v.x = acc[i][0] + bv4.x; v.y = acc[i][1] + bv4.y;
        v.z = acc[i][2] + bv4.z; v.w = acc[i][3] + bv4.w;
        *(float4*)&C[(size_t)(m0 + tm + i) * ldc + n0 + tn] = v;
    }
}

// ---------------- precompute ------------------------------------------------
__global__ void k_prep1(const float* __restrict__ Wh, const float* __restrict__ Wv,
                        const float* __restrict__ Wa, const float* __restrict__ bi,
                        const float* __restrict__ ba, const float* __restrict__ bv,
                        const float* __restrict__ Wq, const float* __restrict__ bq)
{
    int idx = blockIdx.x * blockDim.x + threadIdx.x;
    if (idx < 512 * 2048) g_WhWa[idx] = Wh[idx];
    if (idx < 512 * 512) { int r = idx >> 9, c = idx & 511; g_WvT[idx] = Wv[c * 512 + r]; }
    if (idx < W_ * BH) g_Cbuf[idx] = 0.f;
    if (idx < B_ * 1024) g_HA[idx] = 0.f;
    if (idx < BH) { g_h[idx] = 0.f; g_c[idx] = 0.f; }
    if (idx < G4) {
        float s = 0.f;
        for (int k = 0; k < 512; k++) s += bv[k] * Wa[k * 2048 + idx];
        g_bia[idx] = bi[idx] + ba[idx] + s;
    }
    if (idx < H_) {
        float s = 0.f, s2 = 0.f;
        for (int k = 0; k < 512; k++) {
            s  += Wq[(128 + idx) * 512 + k] * bv[k];
            s2 += bq[k] * Wv[idx * 512 + k];
        }
        g_wqb[idx] = s; g_bqv[idx] = s2;
    }
    if (idx < I_) {
        float s = 0.f;
        for (int k = 0; k < 512; k++) s += Wq[idx * 512 + k] * bv[k];
        g_u[idx] = s;
    }
    if (idx == 0) {
        float s = 0.f;
        for (int k = 0; k < 512; k++) s += bq[k] * bv[k];
        g_sbq = s;
    }
}

__global__ void k_prep2(const float* __restrict__ Wv, const float* __restrict__ Wa,
                        const float* __restrict__ Wq)
{
    int z = blockIdx.z;
    if (z == 0) {
        gemm_body(Wv, 512, Wa, G4, g_WhWa + 512 * G4, G4, 0,
                  blockIdx.y * 64, blockIdx.x * 64, 32);
    } else if (z == 1) {
        if (blockIdx.x < 8)
            gemm_body(Wq + 128 * 512, 512, g_WvT, 512, g_Wqv, 512, 0,
                      blockIdx.y * 64, blockIdx.x * 64, 32);
    } else {
        if (blockIdx.x < 8 && blockIdx.y < 2)
            gemm_body(Wq, 512, g_WvT, 512, g_Wqxv, 512, 0,
                      blockIdx.y * 64, blockIdx.x * 64, 32);
    }
}

__global__ void k_xwi(const float* __restrict__ x, const float* __restrict__ Wi)
{
    gemm_body(x, I_, Wi, G4, g_XWi, G4, g_bia, blockIdx.y * 64, blockIdx.x * 64, 8);
}
__global__ void k_xqv(const float* __restrict__ x)
{
    gemm_body(x, I_, g_Wqxv, H_, g_XQV, H_, 0, blockIdx.y * 64, blockIdx.x * 64, 8);
}

// ---------------- software grid barrier -------------------------------------
__device__ __forceinline__ void gbar(unsigned &ep)
{
    ep++;
    __syncthreads();
    __threadfence();
    if (threadIdx.x == 0) g_flags[blockIdx.x * 32] = ep;
    if (threadIdx.x < NCTA) {
        while (g_flags[threadIdx.x * 32] < ep) __nanosleep(64);
    }
    __threadfence();
    __syncthreads();
}

// ---------------- persistent scan kernel ------------------------------------
__global__ void __launch_bounds__(256, 1)
k_scan(const float* __restrict__ x, float* __restrict__ out)
{
    const int bid = blockIdx.x, tid = threadIdx.x;
    unsigned ep = g_flags[bid * 32];

    __shared__ float sQv[H_];
    __shared__ float sred[256];
    __shared__ float sp[W_];

    for (int t = 0; t < T_; t++) {
        // -------- Phase A: Qv partials = h @ Wqv (split-K 8) --------
        if (bid < 128) {
            int s = bid & 7, mt = (bid >> 3) & 1, nt = bid >> 4;
            gemm_body(g_h + s * 64, H_, g_Wqv + (size_t)s * 64 * H_, H_,
                      g_Qp + (size_t)s * BH, H_, 0, mt * 64, nt * 64, 4);
        }
        gbar(ep);

        // -------- Phase B: attention per batch row --------
        if (bid < 128) {
            const int b = bid;
            const int nv = (t + 1 < W_) ? (t + 1) : W_;
            // reduce Qv partials + precomputed parts
            for (int k = tid; k < H_; k += 256) {
                float q = g_XQV[((size_t)t * B_ + b) * H_ + k] + g_bqv[k];
#pragma unroll
                for (int s = 0; s < 8; s++) q += g_Qp[(size_t)s * BH + b * H_ + k];
                sQv[k] = q;
            }
            // qb = Q.bv = x.u + h.wqb + bq.bv
            float acc = 0.f;
            for (int k = tid; k < H_; k += 256) acc += g_h[b * H_ + k] * g_wqb[k];
            for (int i = tid; i < I_; i += 256) acc += x[((size_t)t * B_ + b) * I_ + i] * g_u[i];
            sred[tid] = acc;
            __syncthreads();
            for (int s = 128; s > 0; s >>= 1) {
                if (tid < s) sred[tid] += sred[tid + s];
                __syncthreads();
            }
            float qb = sred[0] + g_sbq;
            // scores_w = (Qv . Cbuf_w + qb) * inv_sqrt_dk
            int w = tid >> 4, l = tid & 15;
            float dot = 0.f;
            const float* Cw = g_Cbuf + ((size_t)w * B_ + b) * H_;
            for (int k = l; k < H_; k += 16) dot += sQv[k] * Cw[k];
            dot += __shfl_xor_sync(0xffffffffu, dot, 8);
            dot += __shfl_xor_sync(0xffffffffu, dot, 4);
            dot += __shfl_xor_sync(0xffffffffu, dot, 2);
            dot += __shfl_xor_sync(0xffffffffu, dot, 1);
            if (l == 0) sp[w] = (dot + qb) * INV_SQRT_DK;
            __syncthreads();
            if (tid == 0) {
                float m = -1e30f;
                for (int i = 0; i < nv; i++) m = fmaxf(m, sp[i]);
                float pv[W_]; float d = 0.f;
                for (int i = 0; i < nv; i++) { pv[i] = expf(sp[i] - m); d += pv[i]; }
                float inv = 1.f / d;
                for (int i = 0; i < W_; i++) sp[i] = (i < nv) ? pv[i] * inv : 0.f;
            }
            __syncthreads();
            // cbar = sum_w p_w * Cbuf_w  -> HA[:, 512:1024]
            for (int k = tid; k < H_; k += 256) {
                float a = 0.f;
#pragma unroll
                for (int w2 = 0; w2 < W_; w2++)
                    a += sp[w2] * g_Cbuf[((size_t)w2 * B_ + b) * H_ + k];
                g_HA[b * 1024 + H_ + k] = a;
            }
        }
        gbar(ep);

        // -------- Phase C: preact partials = [h|cbar] @ [Wh;Wva] (split-K 2)
        if (bid < 128) {
            int s = bid & 1, mt = (bid >> 1) & 1, nt = bid >> 2;
            gemm_body(g_HA + s * 512, 1024, g_WhWa + (size_t)s * 512 * G4, G4,
                      g_Pre + (size_t)s * B_ * G4, G4, 0, mt * 64, nt * 64, 32);
        }
        gbar(ep);

        // -------- Phase D: gates, cell update, output --------
        for (int idx = bid * 256 + tid; idx < BH; idx += NCTA * 256) {
            int b = idx >> 9, k = idx & (H_ - 1);
            const float* xw = g_XWi + ((size_t)t * B_ + b) * G4;
            float pi = xw[k], pf = xw[k + 512], po = xw[k + 1024], pg = xw[k + 1536];
#pragma unroll
            for (int s = 0; s < 2; s++) {
                const float* pp = g_Pre + ((size_t)s * B_ + b) * G4;
                pi += pp[k]; pf += pp[k + 512]; po += pp[k + 1024]; pg += pp[k + 1536];
            }
            float ig = 1.f / (1.f + expf(-pi));
            float fg = 1.f / (1.f + expf(-pf));
            float og = 1.f / (1.f + expf(-po));
            float gg = tanhf(pg);
            float cn = g_c[idx] * fg + ig * gg;
            float hn = og * tanhf(cn);
            g_c[idx] = cn;
            g_h[idx] = hn;
            g_Cbuf[((size_t)((t + 1) & (W_ - 1)) * B_ + b) * H_ + k] = cn;
            g_HA[b * 1024 + k] = hn;
            out[(size_t)t * BH + idx] = hn;
        }
        gbar(ep);
    }
}

// ---------------- launch ----------------------------------------------------
extern "C" void kernel_launch(void* const* d_in, const int* in_sizes, int n_in,
                              void* d_out, int out_size)
{
    const float* x  = (const float*)d_in[0];
    const float* Wi = (const float*)d_in[1];
    const float* bi = (const float*)d_in[2];
    const float* Wh = (const float*)d_in[3];
    const float* Wv = (const float*)d_in[4];
    const float* bv = (const float*)d_in[5];
    const float* Wq = (const float*)d_in[6];
    const float* bq = (const float*)d_in[7];
    const float* Wa = (const float*)d_in[8];
    const float* ba = (const float*)d_in[9];
    float* out = (float*)d_out;

    k_prep1<<<4096, 256>>>(Wh, Wv, Wa, bi, ba, bv, Wq, bq);
    k_prep2<<<dim3(32, 8, 3), 256>>>(Wv, Wa, Wq);
    k_xwi<<<dim3(32, 256, 1), 256>>>(x, Wi);
    k_xqv<<<dim3(8, 256, 1), 256>>>(x);
    k_scan<<<NCTA, 256>>>(x, out);
}

// round 9
// speedup vs baseline: 1.2420x; 1.2420x over previous
#include <cuda_runtime.h>
#include <cuda_bf16.h>
#include <math.h>

#define T_  128
#define B_  128
#define I_  128
#define H_  512
#define W_  16
#define G4  2048
#define BH  65536
#define TB  16384
#define NCTA 148
#define INV_SQRT_DK 0.04419417382415922f

typedef __nv_bfloat16 bf16;

// ---------------- device scratch (static) -----------------------------------
__device__ __align__(16) float g_XWi[(size_t)TB * G4];   // x@Wi + (bi+ba+bv@Wa)
__device__ __align__(16) float g_XQV[(size_t)TB * H_];   // x@(Wqx@WvT)
__device__ __align__(16) float g_WhWa[1024 * G4];        // fp32 [Wh ; Wv@Wa]
__device__ __align__(16) float g_Wqv[H_ * H_];           // fp32 Wqh@WvT
__device__ __align__(16) float g_Wqxv[I_ * H_];          // fp32 Wqx@WvT
__device__ __align__(16) float g_WvT[H_ * H_];
__device__ __align__(16) float g_bia[G4];
__device__ __align__(16) float g_bqv[H_];
__device__ __align__(16) float g_wqb[H_];
__device__ __align__(16) float g_u[I_];
__device__ float g_sbq;
__device__ __align__(16) float g_h[BH];
__device__ __align__(16) float g_c[BH];
__device__ __align__(16) float g_Cbuf[W_ * BH];
__device__ __align__(16) float g_Qp[8 * BH];
__device__ __align__(16) float g_Pre[2 * B_ * G4];
__device__ volatile unsigned g_flags[NCTA * 32];

// hi/lo bf16 split operands
__device__ __align__(16) bf16 g_xh[(size_t)TB * I_],  g_xl[(size_t)TB * I_];
__device__ __align__(16) bf16 g_Wih[I_ * G4],         g_Wil[I_ * G4];
__device__ __align__(16) bf16 g_WhWah[1024 * G4],     g_WhWal[1024 * G4];
__device__ __align__(16) bf16 g_Wqvh[H_ * H_],        g_Wqvl[H_ * H_];
__device__ __align__(16) bf16 g_Wqxvh[I_ * H_],       g_Wqxvl[I_ * H_];
__device__ __align__(16) bf16 g_HAh[B_ * 1024],       g_HAl[B_ * 1024];

// ---------------- small helpers ---------------------------------------------
__device__ __forceinline__ void split_bf16(float v, bf16* ph, bf16* pl) {
    bf16 h = __float2bfloat16(v);
    *ph = h;
    *pl = __float2bfloat16(v - __bfloat162float(h));
}

__device__ __forceinline__ unsigned smem_u32(const void* p) {
    return (unsigned)__cvta_generic_to_shared(p);
}
__device__ __forceinline__ void ldsm_x4(unsigned addr, unsigned& r0, unsigned& r1,
                                        unsigned& r2, unsigned& r3) {
    asm volatile("ldmatrix.sync.aligned.m8n8.x4.shared.b16 {%0,%1,%2,%3}, [%4];"
                 : "=r"(r0), "=r"(r1), "=r"(r2), "=r"(r3) : "r"(addr));
}
__device__ __forceinline__ void ldsm_x4_t(unsigned addr, unsigned& r0, unsigned& r1,
                                          unsigned& r2, unsigned& r3) {
    asm volatile("ldmatrix.sync.aligned.m8n8.x4.trans.shared.b16 {%0,%1,%2,%3}, [%4];"
                 : "=r"(r0), "=r"(r1), "=r"(r2), "=r"(r3) : "r"(addr));
}
__device__ __forceinline__ void mma16816(float* c, const unsigned* a, unsigned b0, unsigned b1) {
    asm volatile("mma.sync.aligned.m16n8k16.row.col.f32.bf16.bf16.f32 "
                 "{%0,%1,%2,%3}, {%4,%5,%6,%7}, {%8,%9}, {%0,%1,%2,%3};"
                 : "+f"(c[0]), "+f"(c[1]), "+f"(c[2]), "+f"(c[3])
                 : "r"(a[0]), "r"(a[1]), "r"(a[2]), "r"(a[3]), "r"(b0), "r"(b1));
}

// ---------------- bf16-split tensor-core GEMM: 64x64 tile, 256 thr ----------
// C[m0:m0+64, n0:n0+64] = A[m0:, k0:k0+16*nk] @ B[k0:, n0:]  (+bias)
// A row-major (hi/lo), B row-major k x n (hi/lo). 3-pass split: hh + hl + lh.
__device__ __forceinline__ void gemm_mma(
    const bf16* __restrict__ Ah, const bf16* __restrict__ Al, int lda,
    const bf16* __restrict__ Bh, const bf16* __restrict__ Bl, int ldb,
    float* __restrict__ C, int ldc, const float* __restrict__ bias,
    int m0, int n0, int k0, int nk)
{
    __shared__ __align__(16) bf16 As[2][2][64][24];  // [buf][hi/lo][m][k(16,pad24)]
    __shared__ __align__(16) bf16 Bs[2][2][16][72];  // [buf][hi/lo][k][n(64,pad72)]
    const int tid = threadIdx.x;
    const int lane = tid & 31, wid = tid >> 5;
    const int wm = wid & 1;        // warp row: m offset wm*32
    const int wn = wid >> 1;       // warp col: n offset wn*16

    // global load pointers (per-thread)
    const bf16* pAh = Ah + (size_t)(m0 + (tid >> 2)) * lda + k0 + (tid & 3) * 4;
    const bf16* pAl = Al + (size_t)(m0 + (tid >> 2)) * lda + k0 + (tid & 3) * 4;
    const bf16* pBh = Bh + (size_t)(k0 + (tid >> 4)) * ldb + n0 + (tid & 15) * 4;
    const bf16* pBl = Bl + (size_t)(k0 + (tid >> 4)) * ldb + n0 + (tid & 15) * 4;

    uint2 ra_h = *(const uint2*)pAh;
    uint2 ra_l = *(const uint2*)pAl;
    uint2 rb_h = *(const uint2*)pBh;
    uint2 rb_l = *(const uint2*)pBl;

    float acc[2][2][4];
#pragma unroll
    for (int i = 0; i < 2; i++)
#pragma unroll
        for (int j = 0; j < 2; j++)
#pragma unroll
            for (int q = 0; q < 4; q++) acc[i][j][q] = 0.f;

    const int arow = wm * 32 + (lane & 7) + ((lane >> 3) & 1) * 8;
    const int acol = (lane >> 4) * 8;
    const int brow = (lane & 7) + ((lane >> 3) & 1) * 8;
    const int bcol = wn * 16 + (lane >> 4) * 8;

    int buf = 0;
    for (int kt = 0; kt < nk; kt++) {
        *(uint2*)&As[buf][0][tid >> 2][(tid & 3) * 4] = ra_h;
        *(uint2*)&As[buf][1][tid >> 2][(tid & 3) * 4] = ra_l;
        *(uint2*)&Bs[buf][0][tid >> 4][(tid & 15) * 4] = rb_h;
        *(uint2*)&Bs[buf][1][tid >> 4][(tid & 15) * 4] = rb_l;
        __syncthreads();
        if (kt + 1 < nk) {
            ra_h = *(const uint2*)(pAh + (kt + 1) * 16);
            ra_l = *(const uint2*)(pAl + (kt + 1) * 16);
            rb_h = *(const uint2*)(pBh + (size_t)(kt + 1) * 16 * ldb);
            rb_l = *(const uint2*)(pBl + (size_t)(kt + 1) * 16 * ldb);
        }
        // fragments
        unsigned a[2][2][4];  // [hi/lo][mtile][4]
        unsigned b[2][4];     // [hi/lo][b0,b1 for nt0; b0,b1 for nt1]
#pragma unroll
        for (int h = 0; h < 2; h++) {
#pragma unroll
            for (int mt = 0; mt < 2; mt++)
                ldsm_x4(smem_u32(&As[buf][h][arow + mt * 16][acol]),
                        a[h][mt][0], a[h][mt][1], a[h][mt][2], a[h][mt][3]);
            ldsm_x4_t(smem_u32(&Bs[buf][h][brow][bcol]),
                      b[h][0], b[h][1], b[h][2], b[h][3]);
        }
#pragma unroll
        for (int mt = 0; mt < 2; mt++)
#pragma unroll
            for (int nt = 0; nt < 2; nt++) {
                mma16816(acc[mt][nt], a[0][mt], b[0][2 * nt], b[0][2 * nt + 1]); // hh
                mma16816(acc[mt][nt], a[0][mt], b[1][2 * nt], b[1][2 * nt + 1]); // hl
                mma16816(acc[mt][nt], a[1][mt], b[0][2 * nt], b[0][2 * nt + 1]); // lh
            }
        buf ^= 1;
        __syncthreads();
    }
#pragma unroll
    for (int mt = 0; mt < 2; mt++)
#pragma unroll
        for (int nt = 0; nt < 2; nt++) {
            int row = m0 + wm * 32 + mt * 16 + (lane >> 2);
            int col = n0 + wn * 16 + nt * 8 + 2 * (lane & 3);
            float bx = 0.f, by = 0.f;
            if (bias) { bx = bias[col]; by = bias[col + 1]; }
            *(float2*)&C[(size_t)row * ldc + col] =
                make_float2(acc[mt][nt][0] + bx, acc[mt][nt][1] + by);
            *(float2*)&C[(size_t)(row + 8) * ldc + col] =
                make_float2(acc[mt][nt][2] + bx, acc[mt][nt][3] + by);
        }
}

// ---------------- fp32 tiled GEMM (kept for small weight-product prep) ------
__device__ __forceinline__ void gemm_body(
    const float* __restrict__ A, int lda,
    const float* __restrict__ B, int ldb,
    float* __restrict__ C, int ldc,
    const float* __restrict__ bias,
    int m0, int n0, int nk)
{
    __shared__ float As[2][16][68];
    __shared__ float Bs[2][16][64];
    const int tid = threadIdx.x;
    const int ar = tid >> 2;
    const int ac = (tid & 3) << 2;
    const int br = tid >> 4;
    const int bc = (tid & 15) << 2;
    const float* Aptr = A + (size_t)(m0 + ar) * lda + ac;
    const float* Bptr = B + (size_t)br * ldb + n0 + bc;
    float4 ra = *(const float4*)Aptr;
    float4 rb = *(const float4*)Bptr;
    const int tm = (tid >> 4) << 2;
    const int tn = (tid & 15) << 2;
    float acc[4][4];
#pragma unroll
    for (int i = 0; i < 4; i++)
#pragma unroll
        for (int j = 0; j < 4; j++) acc[i][j] = 0.f;

    int buf = 0;
    for (int kt = 0; kt < nk; kt++) {
        As[buf][ac + 0][ar] = ra.x;
        As[buf][ac + 1][ar] = ra.y;
        As[buf][ac + 2][ar] = ra.z;
        As[buf][ac + 3][ar] = ra.w;
        *(float4*)&Bs[buf][br][bc] = rb;
        __syncthreads();
        if (kt + 1 < nk) {
            ra = *(const float4*)(Aptr + (kt + 1) * 16);
            rb = *(const float4*)(Bptr + (size_t)(kt + 1) * 16 * ldb);
        }
#pragma unroll
        for (int kk = 0; kk < 16; kk++) {
            float4 a = *(const float4*)(&As[buf][kk][tm]);
            float4 b = *(const float4*)(&Bs[buf][kk][tn]);
            acc[0][0] += a.x * b.x; acc[0][1] += a.x * b.y; acc[0][2] += a.x * b.z; acc[0][3] += a.x * b.w;
            acc[1][0] += a.y * b.x; acc[1][1] += a.y * b.y; acc[1][2] += a.y * b.z; acc[1][3] += a.y * b.w;
            acc[2][0] += a.z * b.x; acc[2][1] += a.z * b.y; acc[2][2] += a.z * b.z; acc[2][3] += a.z * b.w;
            acc[3][0] += a.w * b.x; acc[3][1] += a.w * b.y; acc[3][2] += a.w * b.z; acc[3][3] += a.w * b.w;
        }
        buf ^= 1;
    }
#pragma unroll
    for (int i = 0; i < 4; i++) {
        float4 v;
        v.x = acc[i][0]; v.y = acc[i][1]; v.z = acc[i][2]; v.w = acc[i][3];
        *(float4*)&C[(size_t)(m0 + tm + i) * ldc + n0 + tn] = v;
    }
}

// ---------------- precompute ------------------------------------------------
__global__ void k_prep1(const float* __restrict__ Wh, const float* __restrict__ Wv,
                        const float* __restrict__ Wa, const float* __restrict__ bi,
                        const float* __restrict__ ba, const float* __restrict__ bv,
                        const float* __restrict__ Wq, const float* __restrict__ bq)
{
    int idx = blockIdx.x * blockDim.x + threadIdx.x;
    if (idx < 512 * 2048) g_WhWa[idx] = Wh[idx];
    if (idx < 512 * 512) { int r = idx >> 9, c = idx & 511; g_WvT[idx] = Wv[c * 512 + r]; }
    if (idx < W_ * BH) g_Cbuf[idx] = 0.f;
    if (idx < B_ * 1024) { g_HAh[idx] = __float2bfloat16(0.f); g_HAl[idx] = __float2bfloat16(0.f); }
    if (idx < BH) { g_h[idx] = 0.f; g_c[idx] = 0.f; }
    if (idx < G4) {
        float s = 0.f;
        for (int k = 0; k < 512; k++) s += bv[k] * Wa[k * 2048 + idx];
        g_bia[idx] = bi[idx] + ba[idx] + s;
    }
    if (idx < H_) {
        float s = 0.f, s2 = 0.f;
        for (int k = 0; k < 512; k++) {
            s  += Wq[(128 + idx) * 512 + k] * bv[k];
            s2 += bq[k] * Wv[idx * 512 + k];
        }
        g_wqb[idx] = s; g_bqv[idx] = s2;
    }
    if (idx < I_) {
        float s = 0.f;
        for (int k = 0; k < 512; k++) s += Wq[idx * 512 + k] * bv[k];
        g_u[idx] = s;
    }
    if (idx == 0) {
        float s = 0.f;
        for (int k = 0; k < 512; k++) s += bq[k] * bv[k];
        g_sbq = s;
    }
}

// weight-product GEMMs in fp32 (small, one-time)
__global__ void k_prep2(const float* __restrict__ Wv, const float* __restrict__ Wa,
                        const float* __restrict__ Wq)
{
    int z = blockIdx.z;
    if (z == 0) {
        gemm_body(Wv, 512, Wa, G4, g_WhWa + 512 * G4, G4, 0,
                  blockIdx.y * 64, blockIdx.x * 64, 32);
    } else if (z == 1) {
        if (blockIdx.x < 8)
            gemm_body(Wq + 128 * 512, 512, g_WvT, 512, g_Wqv, 512, 0,
                      blockIdx.y * 64, blockIdx.x * 64, 32);
    } else {
        if (blockIdx.x < 8 && blockIdx.y < 2)
            gemm_body(Wq, 512, g_WvT, 512, g_Wqxv, 512, 0,
                      blockIdx.y * 64, blockIdx.x * 64, 32);
    }
}

// convert inputs to hi/lo bf16
__global__ void k_cvt1(const float* __restrict__ x, const float* __restrict__ Wi)
{
    size_t stride = (size_t)gridDim.x * blockDim.x;
    for (size_t i = blockIdx.x * blockDim.x + threadIdx.x; i < (size_t)TB * I_; i += stride)
        split_bf16(x[i], &g_xh[i], &g_xl[i]);
    for (size_t i = blockIdx.x * blockDim.x + threadIdx.x; i < (size_t)I_ * G4; i += stride)
        split_bf16(Wi[i], &g_Wih[i], &g_Wil[i]);
}
// convert derived weights to hi/lo bf16 (after k_prep2)
__global__ void k_cvt2()
{
    size_t stride = (size_t)gridDim.x * blockDim.x;
    for (size_t i = blockIdx.x * blockDim.x + threadIdx.x; i < (size_t)1024 * G4; i += stride)
        split_bf16(g_WhWa[i], &g_WhWah[i], &g_WhWal[i]);
    for (size_t i = blockIdx.x * blockDim.x + threadIdx.x; i < (size_t)H_ * H_; i += stride)
        split_bf16(g_Wqv[i], &g_Wqvh[i], &g_Wqvl[i]);
    for (size_t i = blockIdx.x * blockDim.x + threadIdx.x; i < (size_t)I_ * H_; i += stride)
        split_bf16(g_Wqxv[i], &g_Wqxvh[i], &g_Wqxvl[i]);
}

// big x GEMMs on tensor cores
__global__ void k_xwi(void)
{   // g_XWi = x @ Wi + bia : (16384 x 2048, K=128)
    gemm_mma(g_xh, g_xl, I_, g_Wih, g_Wil, G4, g_XWi, G4, g_bia,
             blockIdx.y * 64, blockIdx.x * 64, 0, 8);
}
__global__ void k_xqv(void)
{   // g_XQV = x @ Wqxv : (16384 x 512, K=128)
    gemm_mma(g_xh, g_xl, I_, g_Wqxvh, g_Wqxvl, H_, g_XQV, H_, 0,
             blockIdx.y * 64, blockIdx.x * 64, 0, 8);
}

// ---------------- software grid barrier -------------------------------------
__device__ __forceinline__ void gbar(unsigned& ep)
{
    ep++;
    __syncthreads();
    __threadfence();
    if (threadIdx.x == 0) g_flags[blockIdx.x * 32] = ep;
    if (threadIdx.x < NCTA) {
        while (g_flags[threadIdx.x * 32] < ep) __nanosleep(64);
    }
    __threadfence();
    __syncthreads();
}

// ---------------- persistent scan kernel ------------------------------------
__global__ void __launch_bounds__(256, 1)
k_scan(const float* __restrict__ x, float* __restrict__ out)
{
    const int bid = blockIdx.x, tid = threadIdx.x;
    unsigned ep = g_flags[bid * 32];

    __shared__ float sQv[H_];
    __shared__ float sred[256];
    __shared__ float sp[W_];

    for (int t = 0; t < T_; t++) {
        // -------- Phase A: Qv partials = h @ Wqv  (tensor, split-K 8) -------
        if (bid < 128) {
            int s = bid & 7, mt = (bid >> 3) & 1, nt = bid >> 4;
            gemm_mma(g_HAh, g_HAl, 1024, g_Wqvh, g_Wqvl, H_,
                     g_Qp + (size_t)s * BH, H_, 0,
                     mt * 64, nt * 64, s * 64, 4);
        }
        gbar(ep);

        // -------- Phase B: attention per batch row (fp32) -------------------
        if (bid < 128) {
            const int b = bid;
            const int nv = (t + 1 < W_) ? (t + 1) : W_;
            for (int k = tid; k < H_; k += 256) {
                float q = g_XQV[((size_t)t * B_ + b) * H_ + k] + g_bqv[k];
#pragma unroll
                for (int s = 0; s < 8; s++) q += g_Qp[(size_t)s * BH + b * H_ + k];
                sQv[k] = q;
            }
            float acc = 0.f;
            for (int k = tid; k < H_; k += 256) acc += g_h[b * H_ + k] * g_wqb[k];
            for (int i = tid; i < I_; i += 256) acc += x[((size_t)t * B_ + b) * I_ + i] * g_u[i];
            sred[tid] = acc;
            __syncthreads();
            for (int s = 128; s > 0; s >>= 1) {
                if (tid < s) sred[tid] += sred[tid + s];
                __syncthreads();
            }
            float qb = sred[0] + g_sbq;
            int w = tid >> 4, l = tid & 15;
            float dot = 0.f;
            const float* Cw = g_Cbuf + ((size_t)w * B_ + b) * H_;
            for (int k = l; k < H_; k += 16) dot += sQv[k] * Cw[k];
            dot += __shfl_xor_sync(0xffffffffu, dot, 8);
            dot += __shfl_xor_sync(0xffffffffu, dot, 4);
            dot += __shfl_xor_sync(0xffffffffu, dot, 2);
            dot += __shfl_xor_sync(0xffffffffu, dot, 1);
            if (l == 0) sp[w] = (dot + qb) * INV_SQRT_DK;
            __syncthreads();
            if (tid == 0) {
                float m = -1e30f;
                for (int i = 0; i < nv; i++) m = fmaxf(m, sp[i]);
                float pv[W_]; float d = 0.f;
                for (int i = 0; i < nv; i++) { pv[i] = expf(sp[i] - m); d += pv[i]; }
                float inv = 1.f / d;
                for (int i = 0; i < W_; i++) sp[i] = (i < nv) ? pv[i] * inv : 0.f;
            }
            __syncthreads();
            for (int k = tid; k < H_; k += 256) {
                float a = 0.f;
#pragma unroll
                for (int w2 = 0; w2 < W_; w2++)
                    a += sp[w2] * g_Cbuf[((size_t)w2 * B_ + b) * H_ + k];
                split_bf16(a, &g_HAh[b * 1024 + H_ + k], &g_HAl[b * 1024 + H_ + k]);
            }
        }
        gbar(ep);

        // -------- Phase C: preact = [h|cbar] @ [Wh;Wva] (tensor, split-K 2) -
        if (bid < 128) {
            int s = bid & 1, mt = (bid >> 1) & 1, nt = bid >> 2;
            gemm_mma(g_HAh, g_HAl, 1024, g_WhWah, g_WhWal, G4,
                     g_Pre + (size_t)s * B_ * G4, G4, 0,
                     mt * 64, nt * 64, s * 512, 32);
        }
        gbar(ep);

        // -------- Phase D: gates, cell update, output -----------------------
        for (int idx = bid * 256 + tid; idx < BH; idx += NCTA * 256) {
            int b = idx >> 9, k = idx & (H_ - 1);
            const float* xw = g_XWi + ((size_t)t * B_ + b) * G4;
            float pi = xw[k], pf = xw[k + 512], po = xw[k + 1024], pg = xw[k + 1536];
#pragma unroll
            for (int s = 0; s < 2; s++) {
                const float* pp = g_Pre + ((size_t)s * B_ + b) * G4;
                pi += pp[k]; pf += pp[k + 512]; po += pp[k + 1024]; pg += pp[k + 1536];
            }
            float ig = 1.f / (1.f + expf(-pi));
            float fg = 1.f / (1.f + expf(-pf));
            float og = 1.f / (1.f + expf(-po));
            float gg = tanhf(pg);
            float cn = g_c[idx] * fg + ig * gg;
            float hn = og * tanhf(cn);
            g_c[idx] = cn;
            g_h[idx] = hn;
            g_Cbuf[((size_t)((t + 1) & (W_ - 1)) * B_ + b) * H_ + k] = cn;
            split_bf16(hn, &g_HAh[b * 1024 + k], &g_HAl[b * 1024 + k]);
            out[(size_t)t * BH + idx] = hn;
        }
        gbar(ep);
    }
}

// ---------------- launch ----------------------------------------------------
extern "C" void kernel_launch(void* const* d_in, const int* in_sizes, int n_in,
                              void* d_out, int out_size)
{
    const float* x  = (const float*)d_in[0];
    const float* Wi = (const float*)d_in[1];
    const float* bi = (const float*)d_in[2];
    const float* Wh = (const float*)d_in[3];
    const float* Wv = (const float*)d_in[4];
    const float* bv = (const float*)d_in[5];
    const float* Wq = (const float*)d_in[6];
    const float* bq = (const float*)d_in[7];
    const float* Wa = (const float*)d_in[8];
    const float* ba = (const float*)d_in[9];
    float* out = (float*)d_out;

    k_prep1<<<4096, 256>>>(Wh, Wv, Wa, bi, ba, bv, Wq, bq);
    k_cvt1<<<2048, 256>>>(x, Wi);
    k_prep2<<<dim3(32, 8, 3), 256>>>(Wv, Wa, Wq);
    k_cvt2<<<2048, 256>>>();
    k_xwi<<<dim3(32, 256, 1), 256>>>();
    k_xqv<<<dim3(8, 256, 1), 256>>>();
    k_scan<<<NCTA, 256>>>(x, out);
}

// round 10
// speedup vs baseline: 1.4603x; 1.1758x over previous
#include <cuda_runtime.h>
#include <cuda_bf16.h>
#include <math.h>

#define T_  128
#define B_  128
#define I_  128
#define H_  512
#define W_  16
#define G4  2048
#define BH  65536
#define TB  16384
#define NCTA 148
#define INV_SQRT_DK 0.04419417382415922f

typedef __nv_bfloat16 bf16;

// ---------------- device scratch (static) -----------------------------------
__device__ __align__(16) float g_XWi[(size_t)TB * G4];   // x@Wi_perm + bia_perm (gate-interleaved cols)
__device__ __align__(16) float g_XQV[(size_t)TB * H_];   // x@(Wqx@WvT)
__device__ __align__(16) float g_WhWa[1024 * G4];        // fp32 [Wh ; Wv@Wa] (ORIG col layout)
__device__ __align__(16) float g_Wqv[H_ * H_];           // fp32 Wqh@WvT
__device__ __align__(16) float g_Wqxv[I_ * H_];          // fp32 Wqx@WvT
__device__ __align__(16) float g_WvT[H_ * H_];
__device__ __align__(16) float g_bia[G4];                // permuted
__device__ __align__(16) float g_bqv[H_];
__device__ __align__(16) float g_wqb[H_];
__device__ __align__(16) float g_u[I_];
__device__ float g_sbq;
__device__ __align__(16) float g_h[BH];
__device__ __align__(16) float g_c[BH];
__device__ __align__(16) float g_Cbuf[W_ * BH];
__device__ __align__(16) float g_Qp[8 * BH];
__device__ volatile unsigned g_flags[NCTA * 32];

// hi/lo bf16 split operands
__device__ __align__(16) bf16 g_xh[(size_t)TB * I_],  g_xl[(size_t)TB * I_];
__device__ __align__(16) bf16 g_Wih[I_ * G4],         g_Wil[I_ * G4];     // permuted cols
__device__ __align__(16) bf16 g_WhWah[1024 * G4],     g_WhWal[1024 * G4]; // permuted cols
__device__ __align__(16) bf16 g_Wqvh[H_ * H_],        g_Wqvl[H_ * H_];
__device__ __align__(16) bf16 g_Wqxvh[I_ * H_],       g_Wqxvl[I_ * H_];
__device__ __align__(16) bf16 g_HAh[B_ * 1024],       g_HAl[B_ * 1024];

// ---------------- small helpers ---------------------------------------------
__device__ __forceinline__ void split_bf16(float v, bf16* ph, bf16* pl) {
    bf16 h = __float2bfloat16(v);
    *ph = h;
    *pl = __float2bfloat16(v - __bfloat162float(h));
}
__device__ __forceinline__ unsigned smem_u32(const void* p) {
    return (unsigned)__cvta_generic_to_shared(p);
}
__device__ __forceinline__ void ldsm_x4(unsigned addr, unsigned& r0, unsigned& r1,
                                        unsigned& r2, unsigned& r3) {
    asm volatile("ldmatrix.sync.aligned.m8n8.x4.shared.b16 {%0,%1,%2,%3}, [%4];"
                 : "=r"(r0), "=r"(r1), "=r"(r2), "=r"(r3) : "r"(addr));
}
__device__ __forceinline__ void ldsm_x4_t(unsigned addr, unsigned& r0, unsigned& r1,
                                          unsigned& r2, unsigned& r3) {
    asm volatile("ldmatrix.sync.aligned.m8n8.x4.trans.shared.b16 {%0,%1,%2,%3}, [%4];"
                 : "=r"(r0), "=r"(r1), "=r"(r2), "=r"(r3) : "r"(addr));
}
__device__ __forceinline__ void mma16816(float* c, const unsigned* a, unsigned b0, unsigned b1) {
    asm volatile("mma.sync.aligned.m16n8k16.row.col.f32.bf16.bf16.f32 "
                 "{%0,%1,%2,%3}, {%4,%5,%6,%7}, {%8,%9}, {%0,%1,%2,%3};"
                 : "+f"(c[0]), "+f"(c[1]), "+f"(c[2]), "+f"(c[3])
                 : "r"(a[0]), "r"(a[1]), "r"(a[2]), "r"(a[3]), "r"(b0), "r"(b1));
}

#define POOL64 36864   // smem bytes for 64x64 gemm (4 x 64x72 bf16)

// ---------------- chunked bf16-split MMA GEMM: 64x64 tile, K-chunk 64 -------
// C[m0:+64, n0:+64] = A[m0:, k0:k0+64*nchunk] @ B[k0:, n0:] (+bias)
__device__ __forceinline__ void gemm64(
    char* pool,
    const bf16* __restrict__ Ah, const bf16* __restrict__ Al, int lda,
    const bf16* __restrict__ Bh, const bf16* __restrict__ Bl, int ldb,
    float* __restrict__ C, int ldc, const float* __restrict__ bias,
    int m0, int n0, int k0, int nchunk)
{
    bf16* AsH = (bf16*)pool;
    bf16* AsL = (bf16*)(pool + 9216);
    bf16* BsH = (bf16*)(pool + 18432);
    bf16* BsL = (bf16*)(pool + 27648);
    const int tid = threadIdx.x, lane = tid & 31, wid = tid >> 5;
    const int wm = wid & 1, wn = wid >> 1;

    uint2 rA[2][4], rB[2][4];
#define LOADA64(kt) { _Pragma("unroll") for (int j = 0; j < 4; j++) { \
        int u = tid + j * 256, rr = u >> 4, cc = (u & 15) * 4; \
        rA[0][j] = *(const uint2*)&Ah[(size_t)(m0 + rr) * lda + k0 + (kt) * 64 + cc]; \
        rA[1][j] = *(const uint2*)&Al[(size_t)(m0 + rr) * lda + k0 + (kt) * 64 + cc]; } }
#define LOADB64(kt) { _Pragma("unroll") for (int j = 0; j < 4; j++) { \
        int u = tid + j * 256, rr = u >> 4, cc = (u & 15) * 4; \
        rB[0][j] = *(const uint2*)&Bh[(size_t)(k0 + (kt) * 64 + rr) * ldb + n0 + cc]; \
        rB[1][j] = *(const uint2*)&Bl[(size_t)(k0 + (kt) * 64 + rr) * ldb + n0 + cc]; } }

    float acc[2][2][4];
#pragma unroll
    for (int i = 0; i < 2; i++)
#pragma unroll
        for (int j = 0; j < 2; j++)
#pragma unroll
            for (int q = 0; q < 4; q++) acc[i][j][q] = 0.f;

    const int arow = wm * 32 + (lane & 15);
    const int acol = (lane >> 4) * 8;
    const int brow = lane & 15;
    const int bcol = wn * 16 + (lane >> 4) * 8;

    LOADA64(0); LOADB64(0);
    for (int kt = 0; kt < nchunk; kt++) {
        __syncthreads();
#pragma unroll
        for (int j = 0; j < 4; j++) {
            int u = tid + j * 256, rr = u >> 4, cc = (u & 15) * 4;
            *(uint2*)&AsH[rr * 72 + cc] = rA[0][j];
            *(uint2*)&AsL[rr * 72 + cc] = rA[1][j];
            *(uint2*)&BsH[rr * 72 + cc] = rB[0][j];
            *(uint2*)&BsL[rr * 72 + cc] = rB[1][j];
        }
        __syncthreads();
        if (kt + 1 < nchunk) { LOADA64(kt + 1); LOADB64(kt + 1); }
#pragma unroll
        for (int kk = 0; kk < 4; kk++) {
            unsigned aH[2][4], aL[2][4], bH[4], bL[4];
#pragma unroll
            for (int mt = 0; mt < 2; mt++) {
                ldsm_x4(smem_u32(&AsH[(arow + mt * 16) * 72 + acol + kk * 16]),
                        aH[mt][0], aH[mt][1], aH[mt][2], aH[mt][3]);
                ldsm_x4(smem_u32(&AsL[(arow + mt * 16) * 72 + acol + kk * 16]),
                        aL[mt][0], aL[mt][1], aL[mt][2], aL[mt][3]);
            }
            ldsm_x4_t(smem_u32(&BsH[(kk * 16 + brow) * 72 + bcol]), bH[0], bH[1], bH[2], bH[3]);
            ldsm_x4_t(smem_u32(&BsL[(kk * 16 + brow) * 72 + bcol]), bL[0], bL[1], bL[2], bL[3]);
#pragma unroll
            for (int mt = 0; mt < 2; mt++)
#pragma unroll
                for (int nt = 0; nt < 2; nt++) {
                    mma16816(acc[mt][nt], aH[mt], bH[2 * nt], bH[2 * nt + 1]);
                    mma16816(acc[mt][nt], aH[mt], bL[2 * nt], bL[2 * nt + 1]);
                    mma16816(acc[mt][nt], aL[mt], bH[2 * nt], bH[2 * nt + 1]);
                }
        }
    }
#pragma unroll
    for (int mt = 0; mt < 2; mt++)
#pragma unroll
        for (int nt = 0; nt < 2; nt++) {
            int row = m0 + wm * 32 + mt * 16 + (lane >> 2);
            int col = n0 + wn * 16 + nt * 8 + 2 * (lane & 3);
            float bx = 0.f, by = 0.f;
            if (bias) { bx = bias[col]; by = bias[col + 1]; }
            *(float2*)&C[(size_t)row * ldc + col] =
                make_float2(acc[mt][nt][0] + bx, acc[mt][nt][1] + by);
            *(float2*)&C[(size_t)(row + 8) * ldc + col] =
                make_float2(acc[mt][nt][2] + bx, acc[mt][nt][3] + by);
        }
#undef LOADA64
#undef LOADB64
}

// ---------------- fp32 tiled GEMM (one-time weight products) ----------------
__device__ __forceinline__ void gemm_body(
    const float* __restrict__ A, int lda,
    const float* __restrict__ B, int ldb,
    float* __restrict__ C, int ldc,
    int m0, int n0, int nk)
{
    __shared__ float As[2][16][68];
    __shared__ float Bs[2][16][64];
    const int tid = threadIdx.x;
    const int ar = tid >> 2;
    const int ac = (tid & 3) << 2;
    const int br = tid >> 4;
    const int bc = (tid & 15) << 2;
    const float* Aptr = A + (size_t)(m0 + ar) * lda + ac;
    const float* Bptr = B + (size_t)br * ldb + n0 + bc;
    float4 ra = *(const float4*)Aptr;
    float4 rb = *(const float4*)Bptr;
    const int tm = (tid >> 4) << 2;
    const int tn = (tid & 15) << 2;
    float acc[4][4];
#pragma unroll
    for (int i = 0; i < 4; i++)
#pragma unroll
        for (int j = 0; j < 4; j++) acc[i][j] = 0.f;
    int buf = 0;
    for (int kt = 0; kt < nk; kt++) {
        As[buf][ac + 0][ar] = ra.x;
        As[buf][ac + 1][ar] = ra.y;
        As[buf][ac + 2][ar] = ra.z;
        As[buf][ac + 3][ar] = ra.w;
        *(float4*)&Bs[buf][br][bc] = rb;
        __syncthreads();
        if (kt + 1 < nk) {
            ra = *(const float4*)(Aptr + (kt + 1) * 16);
            rb = *(const float4*)(Bptr + (size_t)(kt + 1) * 16 * ldb);
        }
#pragma unroll
        for (int kk = 0; kk < 16; kk++) {
            float4 a = *(const float4*)(&As[buf][kk][tm]);
            float4 b = *(const float4*)(&Bs[buf][kk][tn]);
            acc[0][0] += a.x * b.x; acc[0][1] += a.x * b.y; acc[0][2] += a.x * b.z; acc[0][3] += a.x * b.w;
            acc[1][0] += a.y * b.x; acc[1][1] += a.y * b.y; acc[1][2] += a.y * b.z; acc[1][3] += a.y * b.w;
            acc[2][0] += a.z * b.x; acc[2][1] += a.z * b.y; acc[2][2] += a.z * b.z; acc[2][3] += a.z * b.w;
            acc[3][0] += a.w * b.x; acc[3][1] += a.w * b.y; acc[3][2] += a.w * b.z; acc[3][3] += a.w * b.w;
        }
        buf ^= 1;
    }
#pragma unroll
    for (int i = 0; i < 4; i++) {
        float4 v;
        v.x = acc[i][0]; v.y = acc[i][1]; v.z = acc[i][2]; v.w = acc[i][3];
        *(float4*)&C[(size_t)(m0 + tm + i) * ldc + n0 + tn] = v;
    }
}

// ---------------- precompute ------------------------------------------------
__global__ void k_prep1(const float* __restrict__ Wh, const float* __restrict__ Wv,
                        const float* __restrict__ Wa, const float* __restrict__ bi,
                        const float* __restrict__ ba, const float* __restrict__ bv,
                        const float* __restrict__ Wq, const float* __restrict__ bq)
{
    int idx = blockIdx.x * blockDim.x + threadIdx.x;
    if (idx < 512 * 2048) g_WhWa[idx] = Wh[idx];
    if (idx < 512 * 512) { int r = idx >> 9, c = idx & 511; g_WvT[idx] = Wv[c * 512 + r]; }
    if (idx < W_ * BH) g_Cbuf[idx] = 0.f;
    if (idx < B_ * 1024) { g_HAh[idx] = __float2bfloat16(0.f); g_HAl[idx] = __float2bfloat16(0.f); }
    if (idx < BH) { g_h[idx] = 0.f; g_c[idx] = 0.f; }
    if (idx < G4) {  // permuted bias: idx = 4*channel + gate
        int g = idx & 3, k = idx >> 2;
        int jo = g * 512 + k;
        float s = 0.f;
        for (int k2 = 0; k2 < 512; k2++) s += bv[k2] * Wa[k2 * 2048 + jo];
        g_bia[idx] = bi[jo] + ba[jo] + s;
    }
    if (idx < H_) {
        float s = 0.f, s2 = 0.f;
        for (int k = 0; k < 512; k++) {
            s  += Wq[(128 + idx) * 512 + k] * bv[k];
            s2 += bq[k] * Wv[idx * 512 + k];
        }
        g_wqb[idx] = s; g_bqv[idx] = s2;
    }
    if (idx < I_) {
        float s = 0.f;
        for (int k = 0; k < 512; k++) s += Wq[idx * 512 + k] * bv[k];
        g_u[idx] = s;
    }
    if (idx == 0) {
        float s = 0.f;
        for (int k = 0; k < 512; k++) s += bq[k] * bv[k];
        g_sbq = s;
    }
}

__global__ void k_prep2(const float* __restrict__ Wv, const float* __restrict__ Wa,
                        const float* __restrict__ Wq)
{
    int z = blockIdx.z;
    if (z == 0) {
        gemm_body(Wv, 512, Wa, G4, g_WhWa + 512 * G4, G4,
                  blockIdx.y * 64, blockIdx.x * 64, 32);
    } else if (z == 1) {
        if (blockIdx.x < 8)
            gemm_body(Wq + 128 * 512, 512, g_WvT, 512, g_Wqv, 512,
                      blockIdx.y * 64, blockIdx.x * 64, 32);
    } else {
        if (blockIdx.x < 8 && blockIdx.y < 2)
            gemm_body(Wq, 512, g_WvT, 512, g_Wqxv, 512,
                      blockIdx.y * 64, blockIdx.x * 64, 32);
    }
}

// convert inputs to hi/lo bf16 (Wi columns permuted)
__global__ void k_cvt1(const float* __restrict__ x, const float* __restrict__ Wi)
{
    size_t stride = (size_t)gridDim.x * blockDim.x;
    for (size_t i = blockIdx.x * blockDim.x + threadIdx.x; i < (size_t)TB * I_; i += stride)
        split_bf16(x[i], &g_xh[i], &g_xl[i]);
    for (size_t i = blockIdx.x * blockDim.x + threadIdx.x; i < (size_t)I_ * G4; i += stride) {
        int r = (int)(i >> 11), jp = (int)(i & 2047);
        int jo = (jp & 3) * 512 + (jp >> 2);
        split_bf16(Wi[r * 2048 + jo], &g_Wih[i], &g_Wil[i]);
    }
}
// convert derived weights (WhWa columns permuted)
__global__ void k_cvt2()
{
    size_t stride = (size_t)gridDim.x * blockDim.x;
    for (size_t i = blockIdx.x * blockDim.x + threadIdx.x; i < (size_t)1024 * G4; i += stride) {
        int r = (int)(i >> 11), jp = (int)(i & 2047);
        int jo = (jp & 3) * 512 + (jp >> 2);
        split_bf16(g_WhWa[r * 2048 + jo], &g_WhWah[i], &g_WhWal[i]);
    }
    for (size_t i = blockIdx.x * blockDim.x + threadIdx.x; i < (size_t)H_ * H_; i += stride)
        split_bf16(g_Wqv[i], &g_Wqvh[i], &g_Wqvl[i]);
    for (size_t i = blockIdx.x * blockDim.x + threadIdx.x; i < (size_t)I_ * H_; i += stride)
        split_bf16(g_Wqxv[i], &g_Wqxvh[i], &g_Wqxvl[i]);
}

// big x GEMMs on tensor cores
__global__ void k_xwi(void)
{
    __shared__ __align__(16) char pool[POOL64];
    gemm64(pool, g_xh, g_xl, I_, g_Wih, g_Wil, G4, g_XWi, G4, g_bia,
           blockIdx.y * 64, blockIdx.x * 64, 0, 2);
}
__global__ void k_xqv(void)
{
    __shared__ __align__(16) char pool[POOL64];
    gemm64(pool, g_xh, g_xl, I_, g_Wqxvh, g_Wqxvl, H_, g_XQV, H_, 0,
           blockIdx.y * 64, blockIdx.x * 64, 0, 2);
}

// ---------------- software grid barrier -------------------------------------
__device__ __forceinline__ void gbar(unsigned& ep)
{
    ep++;
    __syncthreads();
    __threadfence();
    if (threadIdx.x == 0) g_flags[blockIdx.x * 32] = ep;
    if (threadIdx.x < NCTA) {
        while (g_flags[threadIdx.x * 32] < ep) __nanosleep(64);
    }
    __threadfence();
    __syncthreads();
}

// ---------------- persistent scan kernel ------------------------------------
__global__ void __launch_bounds__(256, 1)
k_scan(const float* __restrict__ x, float* __restrict__ out)
{
    const int bid = blockIdx.x, tid = threadIdx.x;
    const int lane = tid & 31, wid = tid >> 5;
    unsigned ep = g_flags[bid * 32];

    __shared__ __align__(16) char pool[POOL64];

    for (int t = 0; t < T_; t++) {
        // ======== Phase A: Qv partials = h @ Wqv (tensor, split-K 8) ========
        if (bid < 128) {
            int s = bid & 7, mt = (bid >> 3) & 1, nt = bid >> 4;
            gemm64(pool, g_HAh, g_HAl, 1024, g_Wqvh, g_Wqvl, H_,
                   g_Qp + (size_t)s * BH, H_, 0,
                   mt * 64, nt * 64, s * 64, 1);
        }
        gbar(ep);

        // ======== Phase B: attention per batch row (fp32) ===================
        if (bid < 128) {
            float* sQv  = (float*)pool;            // 512
            float* sred = (float*)(pool + 2048);   // 256
            float* sp   = (float*)(pool + 3072);   // 16
            const int b = bid;
            const int nv = (t + 1 < W_) ? (t + 1) : W_;
            for (int k = tid; k < H_; k += 256) {
                float q = g_XQV[((size_t)t * B_ + b) * H_ + k] + g_bqv[k];
#pragma unroll
                for (int s = 0; s < 8; s++) q += g_Qp[(size_t)s * BH + b * H_ + k];
                sQv[k] = q;
            }
            float acc = 0.f;
            for (int k = tid; k < H_; k += 256) acc += g_h[b * H_ + k] * g_wqb[k];
            for (int i = tid; i < I_; i += 256) acc += x[((size_t)t * B_ + b) * I_ + i] * g_u[i];
            sred[tid] = acc;
            __syncthreads();
            for (int s = 128; s > 0; s >>= 1) {
                if (tid < s) sred[tid] += sred[tid + s];
                __syncthreads();
            }
            float qb = sred[0] + g_sbq;
            int w = tid >> 4, l = tid & 15;
            float dot = 0.f;
            const float* Cw = g_Cbuf + ((size_t)w * B_ + b) * H_;
            for (int k = l; k < H_; k += 16) dot += sQv[k] * Cw[k];
            dot += __shfl_xor_sync(0xffffffffu, dot, 8);
            dot += __shfl_xor_sync(0xffffffffu, dot, 4);
            dot += __shfl_xor_sync(0xffffffffu, dot, 2);
            dot += __shfl_xor_sync(0xffffffffu, dot, 1);
            if (l == 0) sp[w] = (dot + qb) * INV_SQRT_DK;
            __syncthreads();
            if (tid == 0) {
                float m = -1e30f;
                for (int i = 0; i < nv; i++) m = fmaxf(m, sp[i]);
                float pv[W_]; float d = 0.f;
                for (int i = 0; i < nv; i++) { pv[i] = expf(sp[i] - m); d += pv[i]; }
                float inv = 1.f / d;
                for (int i = 0; i < W_; i++) sp[i] = (i < nv) ? pv[i] * inv : 0.f;
            }
            __syncthreads();
            for (int k = tid; k < H_; k += 256) {
                float a = 0.f;
#pragma unroll
                for (int w2 = 0; w2 < W_; w2++)
                    a += sp[w2] * g_Cbuf[((size_t)w2 * B_ + b) * H_ + k];
                split_bf16(a, &g_HAh[b * 1024 + H_ + k], &g_HAl[b * 1024 + H_ + k]);
            }
        }
        gbar(ep);

        // ======== Phase C+D fused: preact GEMM + cell update ================
        // 128 CTAs: 4 m-tiles (32 rows) x 32 n-tiles (64 permuted cols), full K=1024
        if (bid < 128) {
            const int m0 = (bid & 3) * 32;
            const int n0 = (bid >> 2) * 64;
            bf16* AsH = (bf16*)pool;            // 32x72
            bf16* AsL = (bf16*)(pool + 4608);
            bf16* BsH = (bf16*)(pool + 9216);   // 64x72
            bf16* BsL = (bf16*)(pool + 18432);
            const int wm = wid & 1, wn = wid >> 1;

            uint2 rA[2][2], rB[2][4];
#define LOADA_CD(kt) { _Pragma("unroll") for (int j = 0; j < 2; j++) { \
        int u = tid + j * 256, rr = u >> 4, cc = (u & 15) * 4; \
        rA[0][j] = *(const uint2*)&g_HAh[(size_t)(m0 + rr) * 1024 + (kt) * 64 + cc]; \
        rA[1][j] = *(const uint2*)&g_HAl[(size_t)(m0 + rr) * 1024 + (kt) * 64 + cc]; } }
#define LOADB_CD(kt) { _Pragma("unroll") for (int j = 0; j < 4; j++) { \
        int u = tid + j * 256, rr = u >> 4, cc = (u & 15) * 4; \
        rB[0][j] = *(const uint2*)&g_WhWah[(size_t)((kt) * 64 + rr) * G4 + n0 + cc]; \
        rB[1][j] = *(const uint2*)&g_WhWal[(size_t)((kt) * 64 + rr) * G4 + n0 + cc]; } }

            float acc[2][4];
#pragma unroll
            for (int i = 0; i < 2; i++)
#pragma unroll
                for (int q = 0; q < 4; q++) acc[i][q] = 0.f;

            const int arow = wm * 16 + (lane & 15);
            const int acol = (lane >> 4) * 8;
            const int brow = lane & 15;
            const int bcol = wn * 16 + (lane >> 4) * 8;

            LOADA_CD(0); LOADB_CD(0);
            for (int kt = 0; kt < 16; kt++) {
                __syncthreads();
#pragma unroll
                for (int j = 0; j < 2; j++) {
                    int u = tid + j * 256, rr = u >> 4, cc = (u & 15) * 4;
                    *(uint2*)&AsH[rr * 72 + cc] = rA[0][j];
                    *(uint2*)&AsL[rr * 72 + cc] = rA[1][j];
                }
#pragma unroll
                for (int j = 0; j < 4; j++) {
                    int u = tid + j * 256, rr = u >> 4, cc = (u & 15) * 4;
                    *(uint2*)&BsH[rr * 72 + cc] = rB[0][j];
                    *(uint2*)&BsL[rr * 72 + cc] = rB[1][j];
                }
                __syncthreads();
                if (kt + 1 < 16) { LOADA_CD(kt + 1); LOADB_CD(kt + 1); }
#pragma unroll
                for (int kk = 0; kk < 4; kk++) {
                    unsigned aH[4], aL[4], bH[4], bL[4];
                    ldsm_x4(smem_u32(&AsH[arow * 72 + acol + kk * 16]),
                            aH[0], aH[1], aH[2], aH[3]);
                    ldsm_x4(smem_u32(&AsL[arow * 72 + acol + kk * 16]),
                            aL[0], aL[1], aL[2], aL[3]);
                    ldsm_x4_t(smem_u32(&BsH[(kk * 16 + brow) * 72 + bcol]),
                              bH[0], bH[1], bH[2], bH[3]);
                    ldsm_x4_t(smem_u32(&BsL[(kk * 16 + brow) * 72 + bcol]),
                              bL[0], bL[1], bL[2], bL[3]);
#pragma unroll
                    for (int nt = 0; nt < 2; nt++) {
                        mma16816(acc[nt], aH, bH[2 * nt], bH[2 * nt + 1]);
                        mma16816(acc[nt], aH, bL[2 * nt], bL[2 * nt + 1]);
                        mma16816(acc[nt], aL, bH[2 * nt], bH[2 * nt + 1]);
                    }
                }
            }
#undef LOADA_CD
#undef LOADB_CD
            // epilogue: stage preact tile, then fused cell update
            __syncthreads();
            float* spre = (float*)pool;   // 32 x 64
#pragma unroll
            for (int nt = 0; nt < 2; nt++) {
                int row = wm * 16 + (lane >> 2);
                int col = wn * 16 + nt * 8 + 2 * (lane & 3);
                spre[row * 64 + col]       = acc[nt][0];
                spre[row * 64 + col + 1]   = acc[nt][1];
                spre[(row + 8) * 64 + col]     = acc[nt][2];
                spre[(row + 8) * 64 + col + 1] = acc[nt][3];
            }
            __syncthreads();
            const int slot = (t + 1) & (W_ - 1);
#pragma unroll
            for (int i = 0; i < 2; i++) {
                int pair = tid + i * 256;          // 0..511
                int bl = pair >> 4, ch = pair & 15;
                int b = m0 + bl;
                int Kg = (n0 >> 2) + ch;
                float4 pr = *(float4*)&spre[bl * 64 + 4 * ch];
                float4 xw = *(const float4*)&g_XWi[((size_t)t * B_ + b) * G4 + n0 + 4 * ch];
                float pi = pr.x + xw.x, pf = pr.y + xw.y;
                float po = pr.z + xw.z, pg = pr.w + xw.w;
                float ig = 1.f / (1.f + expf(-pi));
                float fg = 1.f / (1.f + expf(-pf));
                float og = 1.f / (1.f + expf(-po));
                float gg = tanhf(pg);
                int idx = b * H_ + Kg;
                float cn = g_c[idx] * fg + ig * gg;
                float hn = og * tanhf(cn);
                g_c[idx] = cn;
                g_h[idx] = hn;
                g_Cbuf[(size_t)slot * BH + idx] = cn;
                split_bf16(hn, &g_HAh[b * 1024 + Kg], &g_HAl[b * 1024 + Kg]);
                out[(size_t)t * BH + idx] = hn;
            }
        }
        gbar(ep);
    }
}

// ---------------- launch ----------------------------------------------------
extern "C" void kernel_launch(void* const* d_in, const int* in_sizes, int n_in,
                              void* d_out, int out_size)
{
    const float* x  = (const float*)d_in[0];
    const float* Wi = (const float*)d_in[1];
    const float* bi = (const float*)d_in[2];
    const float* Wh = (const float*)d_in[3];
    const float* Wv = (const float*)d_in[4];
    const float* bv = (const float*)d_in[5];
    const float* Wq = (const float*)d_in[6];
    const float* bq = (const float*)d_in[7];
    const float* Wa = (const float*)d_in[8];
    const float* ba = (const float*)d_in[9];
    float* out = (float*)d_out;

    k_prep1<<<4096, 256>>>(Wh, Wv, Wa, bi, ba, bv, Wq, bq);
    k_cvt1<<<2048, 256>>>(x, Wi);
    k_prep2<<<dim3(32, 8, 3), 256>>>(Wv, Wa, Wq);
    k_cvt2<<<2048, 256>>>();
    k_xwi<<<dim3(32, 256, 1), 256>>>();
    k_xqv<<<dim3(8, 256, 1), 256>>>();
    k_scan<<<NCTA, 256>>>(x, out);
}